// round 12
// baseline (speedup 1.0000x reference)
#include <cuda_runtime.h>
#include <cuda_bf16.h>
#include <cuda_fp16.h>
#include <math.h>
#include <stdint.h>

// Problem constants: B=2, H=16 -> BH=32, S=2048, D=64, R=64 -> F=2R=128
#define SQ   2048
#define DH   64
#define FF   128
#define BHN  32
#define TM   128   // query rows per CTA
#define TN   64    // key cols per tile

// ---------------------------------------------------------------------------
// Global scratch. phi pre-scaled by 1/8; phik additionally scaled by sqrt(g_j)
// so E' = E*sqrt(g) and w = fma(E',E',c_j) with c_j = 1e-5*g_j.
// Q/K: single fp16, layout [bh][s][f]. V transposed fp16: [bh][d][s].
// ---------------------------------------------------------------------------
__device__ __half g_phiq_h[(size_t)BHN * SQ * FF];
__device__ __half g_phik_h[(size_t)BHN * SQ * FF];
__device__ __half g_vt_h[(size_t)BHN * DH * SQ];
__device__ float g_gk[BHN * SQ];   // c_j = 1e-5 * exp(||k||^2/16)

// ---------------------------------------------------------------------------
// Helpers (baseline ISA: mma.sync / ldmatrix / cp.async — compiles plain sm_100)
// ---------------------------------------------------------------------------
__device__ __forceinline__ uint32_t smem_u32(const void* p) {
    uint32_t a;
    asm("{ .reg .u64 t; cvta.to.shared.u64 t, %1; cvt.u32.u64 %0, t; }" : "=r"(a) : "l"(p));
    return a;
}
__device__ __forceinline__ void ldsm4(uint32_t* r, uint32_t addr) {
    asm volatile("ldmatrix.sync.aligned.m8n8.x4.shared.b16 {%0,%1,%2,%3}, [%4];"
        : "=r"(r[0]), "=r"(r[1]), "=r"(r[2]), "=r"(r[3]) : "r"(addr));
}
__device__ __forceinline__ void mma_fp16(float* c, const uint32_t* a, uint32_t b0, uint32_t b1) {
    asm volatile("mma.sync.aligned.m16n8k16.row.col.f32.f16.f16.f32 "
        "{%0,%1,%2,%3}, {%4,%5,%6,%7}, {%8,%9}, {%0,%1,%2,%3};"
        : "+f"(c[0]), "+f"(c[1]), "+f"(c[2]), "+f"(c[3])
        : "r"(a[0]), "r"(a[1]), "r"(a[2]), "r"(a[3]), "r"(b0), "r"(b1));
}
__device__ __forceinline__ void cpa16(uint32_t dst, const void* src) {
    asm volatile("cp.async.cg.shared.global [%0], [%1], 16;" :: "r"(dst), "l"(src));
}
#define CP_COMMIT() asm volatile("cp.async.commit_group;" ::: "memory")
#define CP_WAIT1()  asm volatile("cp.async.wait_group 1;" ::: "memory")

// A-operand ldmatrix addrs (16 rows x 16 k at (r0, chunk c0)), row-major,
// xor-swizzled 16B chunks: chunk' = chunk ^ (row & 7)
__device__ __forceinline__ uint32_t addrA(uint32_t base, int r0, int c0, int lane, int rowb) {
    int mi = lane >> 3;
    int row = r0 + (lane & 7) + ((mi & 1) << 3);
    int ch = c0 + (mi >> 1);
    return base + row * rowb + ((ch ^ (row & 7)) << 4);
}
// B-operand (16 n-rows x 16 k at (n0, chunk c0)), n-major
__device__ __forceinline__ uint32_t addrB(uint32_t base, int n0, int c0, int lane, int rowb) {
    int mi = lane >> 3;
    int row = n0 + (lane & 7) + ((mi >> 1) << 3);
    int ch = c0 + (mi & 1);
    return base + row * rowb + ((ch ^ (row & 7)) << 4);
}
__device__ __forceinline__ uint32_t pack_h2(float x, float y) {
    __half2 h = __floats2half2_rn(x, y);
    return *(uint32_t*)&h;
}

// Polynomial sincos (FMA pipe, avoids MUFU bottleneck). |err| ~ 3e-7.
__device__ __forceinline__ void fast_sincos(float a, float* so, float* co) {
    float n = rintf(a * 0.6366197723675814f);          // a * 2/pi
    float r = fmaf(n, -1.57079637050628662109375f, a); // Cody-Waite hi
    r = fmaf(n, 4.37113900018624283e-8f, r);           // Cody-Waite lo
    int q = ((int)n) & 3;
    float r2 = r * r;
    float ps = -1.9841270e-4f;
    ps = fmaf(ps, r2, 8.3333302e-3f);
    ps = fmaf(ps, r2, -1.6666667e-1f);
    float sinr = fmaf(ps * r2, r, r);
    float pc = 2.4801587e-5f;
    pc = fmaf(pc, r2, -1.3888889e-3f);
    pc = fmaf(pc, r2, 4.1666668e-2f);
    pc = fmaf(pc, r2, -0.5f);
    float cosr = fmaf(pc, r2, 1.0f);
    bool swap = q & 1;
    float sv = swap ? cosr : sinr;
    float cv = swap ? sinr : cosr;
    if (q & 2) sv = -sv;
    if ((q + 1) & 2) cv = -cv;
    *so = sv; *co = cv;
}

// ---------------------------------------------------------------------------
// Attn SMEM layout: resident Q fp16 (32KB); 3-stage buffers {K, V, c}
// ---------------------------------------------------------------------------
#define SQH  0
#define BUF0 32768
#define BUFSTRIDE 24832
#define OK   0        // 16384 (K fp16 swizzled, 256B rows)
#define OV   16384    // 8192  (V fp16 swizzled, 128B rows)
#define OGK  24576    // 256   (c_j f32)
#define SMEM_BYTES (32768 + 3 * 24832)   // 107264 -> 2 CTAs/SM

// ---------------------------------------------------------------------------
// Prep: angles = x@W + b (fp32 FFMA, stride-65 xs); phi = [cos,sin]/8 via
// poly sincos from registers; keys: phik *= sqrt(g), g_gk = 1e-5*g.
// blockIdx.z: 0=query, 1=keys.
// ---------------------------------------------------------------------------
__global__ __launch_bounds__(256) void prep_kernel(
    const float* __restrict__ q,
    const float* __restrict__ k,
    const float* __restrict__ W,
    const float* __restrict__ b)
{
    __shared__ float xs[64 * 65];
    __shared__ float sqg[64];

    const int bh = blockIdx.y;
    const int s0 = blockIdx.x * 64;
    const bool is_key = (blockIdx.z == 1);

    const float* src = (is_key ? k : q) + ((size_t)bh * SQ + s0) * DH;

    const int tid = threadIdx.x;
    for (int lin = tid; lin < 64 * 64; lin += 256) {
        int row = lin >> 6, kk = lin & 63;
        xs[row * 65 + kk] = src[lin];
    }
    __syncthreads();

    const int tx = tid & 15, ty = tid >> 4;
    const int tx4 = tx * 4, ty4 = ty * 4;

    float bj[4];
#pragma unroll
    for (int j = 0; j < 4; j++) bj[j] = b[tx4 + j];
    float acc[4][4];
#pragma unroll
    for (int i = 0; i < 4; i++)
#pragma unroll
        for (int j = 0; j < 4; j++) acc[i][j] = bj[j];

#pragma unroll 4
    for (int kk = 0; kk < 64; kk++) {
        float a0 = xs[(ty4 + 0) * 65 + kk];
        float a1 = xs[(ty4 + 1) * 65 + kk];
        float a2 = xs[(ty4 + 2) * 65 + kk];
        float a3 = xs[(ty4 + 3) * 65 + kk];
        const float4 wv = *(const float4*)(W + kk * 64 + tx4);
        acc[0][0] = fmaf(a0, wv.x, acc[0][0]); acc[0][1] = fmaf(a0, wv.y, acc[0][1]);
        acc[0][2] = fmaf(a0, wv.z, acc[0][2]); acc[0][3] = fmaf(a0, wv.w, acc[0][3]);
        acc[1][0] = fmaf(a1, wv.x, acc[1][0]); acc[1][1] = fmaf(a1, wv.y, acc[1][1]);
        acc[1][2] = fmaf(a1, wv.z, acc[1][2]); acc[1][3] = fmaf(a1, wv.w, acc[1][3]);
        acc[2][0] = fmaf(a2, wv.x, acc[2][0]); acc[2][1] = fmaf(a2, wv.y, acc[2][1]);
        acc[2][2] = fmaf(a2, wv.z, acc[2][2]); acc[2][3] = fmaf(a2, wv.w, acc[2][3]);
        acc[3][0] = fmaf(a3, wv.x, acc[3][0]); acc[3][1] = fmaf(a3, wv.y, acc[3][1]);
        acc[3][2] = fmaf(a3, wv.z, acc[3][2]); acc[3][3] = fmaf(a3, wv.w, acc[3][3]);
    }

    if (is_key && tid < 64) {
        float sum = 0.f;
#pragma unroll 8
        for (int kk = 0; kk < 64; kk++) {
            float v = xs[tid * 65 + kk];
            sum = fmaf(v, v, sum);
        }
        sqg[tid] = __expf(sum * (1.0f / 32.0f));
        g_gk[bh * SQ + s0 + tid] = 1e-5f * __expf(sum * (1.0f / 16.0f));
    }
    __syncthreads();   // sqg ready

    // direct epilogue: poly sincos + fp16 pack, coalesced 8B stores
    __half* dst = (is_key ? g_phik_h : g_phiq_h);
#pragma unroll
    for (int i = 0; i < 4; i++) {
        const float scale = is_key ? (0.125f * sqg[ty4 + i]) : 0.125f;
        float c[4], s[4];
#pragma unroll
        for (int j = 0; j < 4; j++) {
            float sv, cv;
            fast_sincos(acc[i][j], &sv, &cv);
            c[j] = cv * scale;
            s[j] = sv * scale;
        }
        size_t idx = ((size_t)bh * SQ + s0 + ty4 + i) * FF;
        uint2 cw = make_uint2(pack_h2(c[0], c[1]), pack_h2(c[2], c[3]));
        uint2 sw = make_uint2(pack_h2(s[0], s[1]), pack_h2(s[2], s[3]));
        *(uint2*)(dst + idx + tx4) = cw;
        *(uint2*)(dst + idx + 64 + tx4) = sw;
    }
}

// ---------------------------------------------------------------------------
// V transpose: V[bh][s][d] f32 -> g_vt_h[bh][d][s] fp16
// ---------------------------------------------------------------------------
__global__ __launch_bounds__(256) void vt_prep_kernel(const float* __restrict__ V)
{
    __shared__ float t[64][65];
    const int bh = blockIdx.y;
    const int s0 = blockIdx.x * 64;
    const int tid = threadIdx.x;

    for (int lin = tid; lin < 4096; lin += 256) {
        int s = lin >> 6, d = lin & 63;
        t[s][d] = V[((size_t)bh * SQ + s0 + s) * DH + d];
    }
    __syncthreads();
    for (int lin = tid; lin < 4096; lin += 256) {
        int d = lin >> 6, s = lin & 63;
        g_vt_h[((size_t)bh * DH + d) * SQ + s0 + s] = __float2half_rn(t[s][d]);
    }
}

// ---------------------------------------------------------------------------
// Attention: CTA = 128 query rows of one (b,h).
// Key tile processed in two 32-col halves: GEMM1h -> epilogue -> GEMM2h.
// E shrinks to 16 live regs -> deeper ldsm pipelining under the 128-reg cap.
// 3-stage cp.async pipeline, one __syncthreads per iteration, 2 CTAs/SM.
// ---------------------------------------------------------------------------
__global__ __launch_bounds__(256, 2) void attn_mma_kernel(
    float* __restrict__ out)
{
    extern __shared__ char smem[];
    const uint32_t base = smem_u32(smem);

    const int tid = threadIdx.x;
    const int wid = tid >> 5;
    const int lane = tid & 31;
    const int it = gridDim.x - 1 - blockIdx.x;   // longest CTAs first
    const int bh = blockIdx.y;
    const int i0 = it * TM;
    const int jt_max = 2 * it + 1;

    const __half* pkh = g_phik_h + (size_t)bh * SQ * FF;
    const __half* vth = g_vt_h + (size_t)bh * DH * SQ;
    const float* gk = g_gk + bh * SQ;

    // --- resident phiQ tile (fp16, swizzled 256B rows) ---
    {
        const __half* pqh = g_phiq_h + ((size_t)bh * SQ + i0) * FF;
        for (int i = tid; i < 128 * 16; i += 256) {
            int row = i >> 4, ch = i & 15;
            uint32_t off = row * 256 + ((ch ^ (row & 7)) << 4);
            *(uint4*)(smem + SQH + off) = *(const uint4*)(pqh + (size_t)row * FF + ch * 8);
        }
    }

    auto issue_tile = [&](int jt) {
        uint32_t buf = base + BUF0 + (uint32_t)(jt % 3) * BUFSTRIDE;
        int j0 = jt * TN;
        for (int i = tid; i < 1024; i += 256) {
            int row = i >> 4, ch = i & 15;
            uint32_t off = row * 256 + ((ch ^ (row & 7)) << 4);
            cpa16(buf + OK + off, pkh + (size_t)(j0 + row) * FF + ch * 8);
        }
        for (int i = tid; i < 512; i += 256) {
            int row = i >> 3, ch = i & 7;
            uint32_t off = row * 128 + ((ch ^ (row & 7)) << 4);
            cpa16(buf + OV + off, vth + (size_t)row * SQ + j0 + ch * 8);
        }
        if (tid < 16) cpa16(buf + OGK + tid * 16, gk + j0 + tid * 4);
    };

    issue_tile(0); CP_COMMIT();
    issue_tile(1); CP_COMMIT();

    float O[8][4];
#pragma unroll
    for (int n = 0; n < 8; n++)
#pragma unroll
        for (int j = 0; j < 4; j++) O[n][j] = 0.f;
    float rs0 = 0.f, rs1 = 0.f;

    const int mrow0 = i0 + wid * 16 + (lane >> 2);
    const int mrow1 = mrow0 + 8;
    const int colq = 2 * (lane & 3);

    for (int jt = 0; jt <= jt_max; jt++) {
        const int j0 = jt * TN;
        const uint32_t buf = base + BUF0 + (uint32_t)(jt % 3) * BUFSTRIDE;

        CP_WAIT1();
        __syncthreads();

        if (jt + 2 <= jt_max) issue_tile(jt + 2);
        CP_COMMIT();

        const float* ckb = (const float*)(smem + BUF0 + (size_t)(jt % 3) * BUFSTRIDE + OGK);

#pragma unroll
        for (int h = 0; h < 2; h++) {
            // ---- GEMM1 half: E (m16 x n32) ----
            float E[4][4];
#pragma unroll
            for (int n = 0; n < 4; n++)
#pragma unroll
                for (int j = 0; j < 4; j++) E[n][j] = 0.f;

#pragma unroll
            for (int ks = 0; ks < 8; ks++) {
                uint32_t a[4];
                ldsm4(a, addrA(base + SQH, wid * 16, 2 * ks, lane, 256));
#pragma unroll
                for (int p = 0; p < 2; p++) {
                    uint32_t bq[4];
                    ldsm4(bq, addrB(buf + OK, (2 * h + p) * 16, 2 * ks, lane, 256));
                    mma_fp16(E[2 * p],     a, bq[0], bq[1]);
                    mma_fp16(E[2 * p + 1], a, bq[2], bq[3]);
                }
            }

            // ---- epilogue half: w = fma(E,E,c); mask only diagonal tiles ----
            const int jbase = j0 + 32 * h;
            if (jbase + 31 <= i0) {
#pragma unroll
                for (int nt = 0; nt < 4; nt++) {
                    float c0 = ckb[32 * h + 8 * nt + colq];
                    float c1 = ckb[32 * h + 8 * nt + colq + 1];
                    float w00 = fmaf(E[nt][0], E[nt][0], c0);
                    float w01 = fmaf(E[nt][1], E[nt][1], c1);
                    float w10 = fmaf(E[nt][2], E[nt][2], c0);
                    float w11 = fmaf(E[nt][3], E[nt][3], c1);
                    E[nt][0] = w00; E[nt][1] = w01; E[nt][2] = w10; E[nt][3] = w11;
                    rs0 += w00 + w01;
                    rs1 += w10 + w11;
                }
            } else {
#pragma unroll
                for (int nt = 0; nt < 4; nt++) {
                    int jc = jbase + 8 * nt + colq;
                    float c0 = ckb[32 * h + 8 * nt + colq];
                    float c1 = ckb[32 * h + 8 * nt + colq + 1];
                    float w00 = fmaf(E[nt][0], E[nt][0], c0);
                    float w01 = fmaf(E[nt][1], E[nt][1], c1);
                    float w10 = fmaf(E[nt][2], E[nt][2], c0);
                    float w11 = fmaf(E[nt][3], E[nt][3], c1);
                    if (jc > mrow0)     w00 = 0.f;
                    if (jc + 1 > mrow0) w01 = 0.f;
                    if (jc > mrow1)     w10 = 0.f;
                    if (jc + 1 > mrow1) w11 = 0.f;
                    E[nt][0] = w00; E[nt][1] = w01; E[nt][2] = w10; E[nt][3] = w11;
                    rs0 += w00 + w01;
                    rs1 += w10 + w11;
                }
            }

            // ---- GEMM2 half: O += w(:,32h..32h+31) . V(32h..,:) ----
#pragma unroll
            for (int sl = 0; sl < 2; sl++) {
                const int s = 2 * h + sl;
                uint32_t ah[4];
                ah[0] = pack_h2(E[2 * sl][0],     E[2 * sl][1]);
                ah[1] = pack_h2(E[2 * sl][2],     E[2 * sl][3]);
                ah[2] = pack_h2(E[2 * sl + 1][0], E[2 * sl + 1][1]);
                ah[3] = pack_h2(E[2 * sl + 1][2], E[2 * sl + 1][3]);
#pragma unroll
                for (int np = 0; np < 4; np++) {
                    uint32_t v[4];
                    ldsm4(v, addrB(buf + OV, np * 16, 2 * s, lane, 128));
                    mma_fp16(O[2 * np],     ah, v[0], v[1]);
                    mma_fp16(O[2 * np + 1], ah, v[2], v[3]);
                }
            }
        }
    }

    // ---- final: reduce row sums across quad lanes, normalize, store ----
    rs0 += __shfl_xor_sync(0xffffffffu, rs0, 1);
    rs0 += __shfl_xor_sync(0xffffffffu, rs0, 2);
    rs1 += __shfl_xor_sync(0xffffffffu, rs1, 1);
    rs1 += __shfl_xor_sync(0xffffffffu, rs1, 2);
    const float inv0 = 1.0f / rs0;
    const float inv1 = 1.0f / rs1;

    float* o0 = out + ((size_t)bh * SQ + mrow0) * DH;
    float* o1 = out + ((size_t)bh * SQ + mrow1) * DH;
#pragma unroll
    for (int nt = 0; nt < 8; nt++) {
        int d = 8 * nt + colq;
        float2 v0 = make_float2(O[nt][0] * inv0, O[nt][1] * inv0);
        float2 v1 = make_float2(O[nt][2] * inv1, O[nt][3] * inv1);
        *(float2*)(o0 + d) = v0;
        *(float2*)(o1 + d) = v1;
    }
}

// ---------------------------------------------------------------------------
extern "C" void kernel_launch(void* const* d_in, const int* in_sizes, int n_in,
                              void* d_out, int out_size)
{
    const float* q = (const float*)d_in[0];
    const float* k = (const float*)d_in[1];
    const float* v = (const float*)d_in[2];
    // d_in[3] = mask (int32) — causal mask reproduced analytically, unused
    const float* W = (const float*)d_in[4];
    const float* b = (const float*)d_in[5];
    float* out = (float*)d_out;
    (void)in_sizes; (void)n_in; (void)out_size;

    cudaFuncSetAttribute(attn_mma_kernel, cudaFuncAttributeMaxDynamicSharedMemorySize, SMEM_BYTES);

    vt_prep_kernel<<<dim3(SQ / 64, BHN), 256>>>(v);
    prep_kernel<<<dim3(SQ / 64, BHN, 2), 256>>>(q, k, W, b);
    attn_mma_kernel<<<dim3(SQ / TM, BHN), 256, SMEM_BYTES>>>(out);
}

// round 13
// speedup vs baseline: 1.0355x; 1.0355x over previous
#include <cuda_runtime.h>
#include <cuda_bf16.h>
#include <cuda_fp16.h>
#include <math.h>
#include <stdint.h>

// Problem constants: B=2, H=16 -> BH=32, S=2048, D=64, R=64 -> F=2R=128
#define SQ   2048
#define DH   64
#define FF   128
#define BHN  32
#define TM   128   // query rows per CTA
#define TN   64    // key cols per tile

// ---------------------------------------------------------------------------
// Global scratch. phi pre-scaled by 1/8; phik additionally scaled by sqrt(g_j)
// so E' = E*sqrt(g) and w = fma(E',E',c_j) with c_j = 1e-5*g_j.
// Q/K: single fp16, layout [bh][s][f]. V transposed fp16: [bh][d][s].
// ---------------------------------------------------------------------------
__device__ __half g_phiq_h[(size_t)BHN * SQ * FF];
__device__ __half g_phik_h[(size_t)BHN * SQ * FF];
__device__ __half g_vt_h[(size_t)BHN * DH * SQ];
__device__ float g_gk[BHN * SQ];   // c_j = 1e-5 * exp(||k||^2/16)

// ---------------------------------------------------------------------------
// Helpers (baseline ISA: mma.sync / ldmatrix / cp.async — compiles plain sm_100)
// ---------------------------------------------------------------------------
__device__ __forceinline__ uint32_t smem_u32(const void* p) {
    uint32_t a;
    asm("{ .reg .u64 t; cvta.to.shared.u64 t, %1; cvt.u32.u64 %0, t; }" : "=r"(a) : "l"(p));
    return a;
}
__device__ __forceinline__ void ldsm4(uint32_t* r, uint32_t addr) {
    asm volatile("ldmatrix.sync.aligned.m8n8.x4.shared.b16 {%0,%1,%2,%3}, [%4];"
        : "=r"(r[0]), "=r"(r[1]), "=r"(r[2]), "=r"(r[3]) : "r"(addr));
}
__device__ __forceinline__ void mma_fp16(float* c, const uint32_t* a, uint32_t b0, uint32_t b1) {
    asm volatile("mma.sync.aligned.m16n8k16.row.col.f32.f16.f16.f32 "
        "{%0,%1,%2,%3}, {%4,%5,%6,%7}, {%8,%9}, {%0,%1,%2,%3};"
        : "+f"(c[0]), "+f"(c[1]), "+f"(c[2]), "+f"(c[3])
        : "r"(a[0]), "r"(a[1]), "r"(a[2]), "r"(a[3]), "r"(b0), "r"(b1));
}
__device__ __forceinline__ void cpa16(uint32_t dst, const void* src) {
    asm volatile("cp.async.cg.shared.global [%0], [%1], 16;" :: "r"(dst), "l"(src));
}
#define CP_COMMIT() asm volatile("cp.async.commit_group;" ::: "memory")
#define CP_WAIT1()  asm volatile("cp.async.wait_group 1;" ::: "memory")

// B-operand ldmatrix addrs (16 n-rows x 16 k at (n0, chunk c0)), n-major,
// xor-swizzled 16B chunks: chunk' = chunk ^ (row & 7)
__device__ __forceinline__ uint32_t addrB(uint32_t base, int n0, int c0, int lane, int rowb) {
    int mi = lane >> 3;
    int row = n0 + (lane & 7) + ((mi >> 1) << 3);
    int ch = c0 + (mi & 1);
    return base + row * rowb + ((ch ^ (row & 7)) << 4);
}
__device__ __forceinline__ uint32_t pack_h2(float x, float y) {
    __half2 h = __floats2half2_rn(x, y);
    return *(uint32_t*)&h;
}

// ---------------------------------------------------------------------------
// Attn SMEM layout: 3-stage buffers {K, V, c} only (Q lives in registers)
// ---------------------------------------------------------------------------
#define BUFSTRIDE 24832
#define OK   0        // 16384 (K fp16 swizzled, 256B rows)
#define OV   16384    // 8192  (V fp16 swizzled, 128B rows)
#define OGK  24576    // 256   (c_j f32)
#define SMEM_BYTES (3 * 24832)   // 74496 -> 2 CTAs/SM

// ---------------------------------------------------------------------------
// Prep (z=0 query, z=1 keys): angles = x@W + b (fp32 FFMA, stride-65 xs);
// phi = [cos,sin]/8 (keys *= sqrt(g)); g_gk = 1e-5*g.
// Prep (z=2): V transpose -> g_vt_h fp16 (overlapped in the same launch).
// ---------------------------------------------------------------------------
__global__ __launch_bounds__(256) void prep_kernel(
    const float* __restrict__ q,
    const float* __restrict__ k,
    const float* __restrict__ v,
    const float* __restrict__ W,
    const float* __restrict__ b)
{
    __shared__ float xs[64 * 65];
    __shared__ float sqg[64];

    const int bh = blockIdx.y;
    const int s0 = blockIdx.x * 64;
    const int z = blockIdx.z;
    const int tid = threadIdx.x;

    if (z == 2) {
        // --- V transpose branch ---
        for (int lin = tid; lin < 4096; lin += 256) {
            int s = lin >> 6, d = lin & 63;
            xs[s * 65 + d] = v[((size_t)bh * SQ + s0 + s) * DH + d];
        }
        __syncthreads();
        for (int lin = tid; lin < 4096; lin += 256) {
            int d = lin >> 6, s = lin & 63;
            g_vt_h[((size_t)bh * DH + d) * SQ + s0 + s] = __float2half_rn(xs[s * 65 + d]);
        }
        return;
    }

    const bool is_key = (z == 1);
    const float* src = (is_key ? k : q) + ((size_t)bh * SQ + s0) * DH;

    for (int lin = tid; lin < 64 * 64; lin += 256) {
        int row = lin >> 6, kk = lin & 63;
        xs[row * 65 + kk] = src[lin];
    }
    __syncthreads();

    const int tx = tid & 15, ty = tid >> 4;
    const int tx4 = tx * 4, ty4 = ty * 4;

    float bj[4];
#pragma unroll
    for (int j = 0; j < 4; j++) bj[j] = b[tx4 + j];
    float acc[4][4];
#pragma unroll
    for (int i = 0; i < 4; i++)
#pragma unroll
        for (int j = 0; j < 4; j++) acc[i][j] = bj[j];

#pragma unroll 4
    for (int kk = 0; kk < 64; kk++) {
        float a0 = xs[(ty4 + 0) * 65 + kk];
        float a1 = xs[(ty4 + 1) * 65 + kk];
        float a2 = xs[(ty4 + 2) * 65 + kk];
        float a3 = xs[(ty4 + 3) * 65 + kk];
        const float4 wv = *(const float4*)(W + kk * 64 + tx4);
        acc[0][0] = fmaf(a0, wv.x, acc[0][0]); acc[0][1] = fmaf(a0, wv.y, acc[0][1]);
        acc[0][2] = fmaf(a0, wv.z, acc[0][2]); acc[0][3] = fmaf(a0, wv.w, acc[0][3]);
        acc[1][0] = fmaf(a1, wv.x, acc[1][0]); acc[1][1] = fmaf(a1, wv.y, acc[1][1]);
        acc[1][2] = fmaf(a1, wv.z, acc[1][2]); acc[1][3] = fmaf(a1, wv.w, acc[1][3]);
        acc[2][0] = fmaf(a2, wv.x, acc[2][0]); acc[2][1] = fmaf(a2, wv.y, acc[2][1]);
        acc[2][2] = fmaf(a2, wv.z, acc[2][2]); acc[2][3] = fmaf(a2, wv.w, acc[2][3]);
        acc[3][0] = fmaf(a3, wv.x, acc[3][0]); acc[3][1] = fmaf(a3, wv.y, acc[3][1]);
        acc[3][2] = fmaf(a3, wv.z, acc[3][2]); acc[3][3] = fmaf(a3, wv.w, acc[3][3]);
    }

    if (is_key && tid < 64) {
        float sum = 0.f;
#pragma unroll 8
        for (int kk = 0; kk < 64; kk++) {
            float vx = xs[tid * 65 + kk];
            sum = fmaf(vx, vx, sum);
        }
        sqg[tid] = __expf(sum * (1.0f / 32.0f));
        g_gk[bh * SQ + s0 + tid] = 1e-5f * __expf(sum * (1.0f / 16.0f));
    }
    __syncthreads();   // sqg ready

    __half* dst = (is_key ? g_phik_h : g_phiq_h);
#pragma unroll
    for (int i = 0; i < 4; i++) {
        const float scale = is_key ? (0.125f * sqg[ty4 + i]) : 0.125f;
        float c[4], s[4];
#pragma unroll
        for (int j = 0; j < 4; j++) {
            float sv, cv;
            __sincosf(acc[i][j], &sv, &cv);
            c[j] = cv * scale;
            s[j] = sv * scale;
        }
        size_t idx = ((size_t)bh * SQ + s0 + ty4 + i) * FF;
        uint2 cw = make_uint2(pack_h2(c[0], c[1]), pack_h2(c[2], c[3]));
        uint2 sw = make_uint2(pack_h2(s[0], s[1]), pack_h2(s[2], s[3]));
        *(uint2*)(dst + idx + tx4) = cw;
        *(uint2*)(dst + idx + 64 + tx4) = sw;
    }
}

// ---------------------------------------------------------------------------
// Attention: CTA = 128 query rows of one (b,h). R11 structure (8 independent
// E chains) + Q fragments persistent in registers (no A-side ldsm at all).
// 3-stage cp.async pipeline, one __syncthreads per iteration, 2 CTAs/SM.
// ---------------------------------------------------------------------------
__global__ __launch_bounds__(256, 2) void attn_mma_kernel(
    float* __restrict__ out)
{
    extern __shared__ char smem[];
    const uint32_t base = smem_u32(smem);

    const int tid = threadIdx.x;
    const int wid = tid >> 5;
    const int lane = tid & 31;
    const int it = gridDim.x - 1 - blockIdx.x;   // longest CTAs first
    const int bh = blockIdx.y;
    const int i0 = it * TM;
    const int jt_max = 2 * it + 1;

    const __half* pkh = g_phik_h + (size_t)bh * SQ * FF;
    const __half* vth = g_vt_h + (size_t)bh * DH * SQ;
    const float* gk = g_gk + bh * SQ;

    auto issue_tile = [&](int jt) {
        uint32_t buf = base + (uint32_t)(jt % 3) * BUFSTRIDE;
        int j0 = jt * TN;
        for (int i = tid; i < 1024; i += 256) {
            int row = i >> 4, ch = i & 15;
            uint32_t off = row * 256 + ((ch ^ (row & 7)) << 4);
            cpa16(buf + OK + off, pkh + (size_t)(j0 + row) * FF + ch * 8);
        }
        for (int i = tid; i < 512; i += 256) {
            int row = i >> 3, ch = i & 7;
            uint32_t off = row * 128 + ((ch ^ (row & 7)) << 4);
            cpa16(buf + OV + off, vth + (size_t)row * SQ + j0 + ch * 8);
        }
        if (tid < 16) cpa16(buf + OGK + tid * 16, gk + j0 + tid * 4);
    };

    issue_tile(0); CP_COMMIT();
    issue_tile(1); CP_COMMIT();

    // --- persistent Q fragments: loaded once from global in frag layout ---
    const int r0 = wid * 16 + (lane >> 2);
    const int colq = 2 * (lane & 3);
    uint32_t qf[8][4];
    {
        const __half* pq = g_phiq_h + ((size_t)bh * SQ + i0) * FF;
#pragma unroll
        for (int ks = 0; ks < 8; ks++) {
            int c0 = 16 * ks + colq;
            qf[ks][0] = *(const uint32_t*)(pq + (size_t)r0 * FF + c0);
            qf[ks][1] = *(const uint32_t*)(pq + (size_t)(r0 + 8) * FF + c0);
            qf[ks][2] = *(const uint32_t*)(pq + (size_t)r0 * FF + c0 + 8);
            qf[ks][3] = *(const uint32_t*)(pq + (size_t)(r0 + 8) * FF + c0 + 8);
        }
    }

    float O[8][4];
#pragma unroll
    for (int n = 0; n < 8; n++)
#pragma unroll
        for (int j = 0; j < 4; j++) O[n][j] = 0.f;
    float rs0 = 0.f, rs1 = 0.f;

    const int mrow0 = i0 + r0;
    const int mrow1 = mrow0 + 8;

    for (int jt = 0; jt <= jt_max; jt++) {
        const int j0 = jt * TN;
        const uint32_t buf = base + (uint32_t)(jt % 3) * BUFSTRIDE;

        CP_WAIT1();
        __syncthreads();

        if (jt + 2 <= jt_max) issue_tile(jt + 2);
        CP_COMMIT();

        // ---- GEMM1: E = Q.K'^T (Q from registers) ----
        float E[8][4];
#pragma unroll
        for (int n = 0; n < 8; n++)
#pragma unroll
            for (int j = 0; j < 4; j++) E[n][j] = 0.f;

#pragma unroll
        for (int ks = 0; ks < 8; ks++) {
#pragma unroll
            for (int np = 0; np < 4; np++) {
                uint32_t bq[4];
                ldsm4(bq, addrB(buf + OK, np * 16, 2 * ks, lane, 256));
                mma_fp16(E[2 * np],     qf[ks], bq[0], bq[1]);
                mma_fp16(E[2 * np + 1], qf[ks], bq[2], bq[3]);
            }
        }

        // ---- epilogue: w = fma(E,E,c_j); mask only on diagonal tiles ----
        const float* ckb = (const float*)(smem + (size_t)(jt % 3) * BUFSTRIDE + OGK);
        if (j0 + TN - 1 <= i0) {
#pragma unroll
            for (int nt = 0; nt < 8; nt++) {
                float c0 = ckb[8 * nt + colq];
                float c1 = ckb[8 * nt + colq + 1];
                float w00 = fmaf(E[nt][0], E[nt][0], c0);
                float w01 = fmaf(E[nt][1], E[nt][1], c1);
                float w10 = fmaf(E[nt][2], E[nt][2], c0);
                float w11 = fmaf(E[nt][3], E[nt][3], c1);
                E[nt][0] = w00; E[nt][1] = w01; E[nt][2] = w10; E[nt][3] = w11;
                rs0 += w00 + w01;
                rs1 += w10 + w11;
            }
        } else {
#pragma unroll
            for (int nt = 0; nt < 8; nt++) {
                int jc = j0 + 8 * nt + colq;
                float c0 = ckb[8 * nt + colq];
                float c1 = ckb[8 * nt + colq + 1];
                float w00 = fmaf(E[nt][0], E[nt][0], c0);
                float w01 = fmaf(E[nt][1], E[nt][1], c1);
                float w10 = fmaf(E[nt][2], E[nt][2], c0);
                float w11 = fmaf(E[nt][3], E[nt][3], c1);
                if (jc > mrow0)     w00 = 0.f;
                if (jc + 1 > mrow0) w01 = 0.f;
                if (jc > mrow1)     w10 = 0.f;
                if (jc + 1 > mrow1) w11 = 0.f;
                E[nt][0] = w00; E[nt][1] = w01; E[nt][2] = w10; E[nt][3] = w11;
                rs0 += w00 + w01;
                rs1 += w10 + w11;
            }
        }

        // ---- GEMM2: O += W.V, single fp16 pass (A frags from registers) ----
#pragma unroll
        for (int s = 0; s < 4; s++) {
            uint32_t ah[4];
            ah[0] = pack_h2(E[2 * s][0],     E[2 * s][1]);
            ah[1] = pack_h2(E[2 * s][2],     E[2 * s][3]);
            ah[2] = pack_h2(E[2 * s + 1][0], E[2 * s + 1][1]);
            ah[3] = pack_h2(E[2 * s + 1][2], E[2 * s + 1][3]);
#pragma unroll
            for (int np = 0; np < 4; np++) {
                uint32_t v[4];
                ldsm4(v, addrB(buf + OV, np * 16, 2 * s, lane, 128));
                mma_fp16(O[2 * np],     ah, v[0], v[1]);
                mma_fp16(O[2 * np + 1], ah, v[2], v[3]);
            }
        }
    }

    // ---- final: reduce row sums across quad lanes, normalize, store ----
    rs0 += __shfl_xor_sync(0xffffffffu, rs0, 1);
    rs0 += __shfl_xor_sync(0xffffffffu, rs0, 2);
    rs1 += __shfl_xor_sync(0xffffffffu, rs1, 1);
    rs1 += __shfl_xor_sync(0xffffffffu, rs1, 2);
    const float inv0 = 1.0f / rs0;
    const float inv1 = 1.0f / rs1;

    float* o0 = out + ((size_t)bh * SQ + mrow0) * DH;
    float* o1 = out + ((size_t)bh * SQ + mrow1) * DH;
#pragma unroll
    for (int nt = 0; nt < 8; nt++) {
        int d = 8 * nt + colq;
        float2 v0 = make_float2(O[nt][0] * inv0, O[nt][1] * inv0);
        float2 v1 = make_float2(O[nt][2] * inv1, O[nt][3] * inv1);
        *(float2*)(o0 + d) = v0;
        *(float2*)(o1 + d) = v1;
    }
}

// ---------------------------------------------------------------------------
extern "C" void kernel_launch(void* const* d_in, const int* in_sizes, int n_in,
                              void* d_out, int out_size)
{
    const float* q = (const float*)d_in[0];
    const float* k = (const float*)d_in[1];
    const float* v = (const float*)d_in[2];
    // d_in[3] = mask (int32) — causal mask reproduced analytically, unused
    const float* W = (const float*)d_in[4];
    const float* b = (const float*)d_in[5];
    float* out = (float*)d_out;
    (void)in_sizes; (void)n_in; (void)out_size;

    cudaFuncSetAttribute(attn_mma_kernel, cudaFuncAttributeMaxDynamicSharedMemorySize, SMEM_BYTES);

    prep_kernel<<<dim3(SQ / 64, BHN, 3), 256>>>(q, k, v, W, b);
    attn_mma_kernel<<<dim3(SQ / TM, BHN), 256, SMEM_BYTES>>>(out);
}

// round 14
// speedup vs baseline: 1.1427x; 1.1035x over previous
#include <cuda_runtime.h>
#include <cuda_bf16.h>
#include <cuda_fp16.h>
#include <math.h>
#include <stdint.h>

// Problem constants: B=2, H=16 -> BH=32, S=2048, D=64, R=64 -> F=2R=128
#define SQ   2048
#define DH   64
#define FF   128
#define BHN  32
#define TM   128   // query rows per CTA
#define TN   64    // key cols per tile

// ---------------------------------------------------------------------------
// Global scratch. phi pre-scaled by 1/8; phik additionally scaled by sqrt(g_j)
// so E' = E*sqrt(g) and w = fma(E',E',c_j) with c_j = 1e-5*g_j.
// Q/K: single fp16, layout [bh][s][f]. V transposed fp16: [bh][d][s].
// ---------------------------------------------------------------------------
__device__ __half g_phiq_h[(size_t)BHN * SQ * FF];
__device__ __half g_phik_h[(size_t)BHN * SQ * FF];
__device__ __half g_vt_h[(size_t)BHN * DH * SQ];
__device__ float g_gk[BHN * SQ];   // c_j = 1e-5 * exp(||k||^2/16)

// ---------------------------------------------------------------------------
// Helpers (baseline ISA: mma.sync / ldmatrix / cp.async — compiles plain sm_100)
// ---------------------------------------------------------------------------
__device__ __forceinline__ uint32_t smem_u32(const void* p) {
    uint32_t a;
    asm("{ .reg .u64 t; cvta.to.shared.u64 t, %1; cvt.u32.u64 %0, t; }" : "=r"(a) : "l"(p));
    return a;
}
__device__ __forceinline__ void ldsm4(uint32_t* r, uint32_t addr) {
    asm volatile("ldmatrix.sync.aligned.m8n8.x4.shared.b16 {%0,%1,%2,%3}, [%4];"
        : "=r"(r[0]), "=r"(r[1]), "=r"(r[2]), "=r"(r[3]) : "r"(addr));
}
__device__ __forceinline__ void mma_fp16(float* c, const uint32_t* a, uint32_t b0, uint32_t b1) {
    asm volatile("mma.sync.aligned.m16n8k16.row.col.f32.f16.f16.f32 "
        "{%0,%1,%2,%3}, {%4,%5,%6,%7}, {%8,%9}, {%0,%1,%2,%3};"
        : "+f"(c[0]), "+f"(c[1]), "+f"(c[2]), "+f"(c[3])
        : "r"(a[0]), "r"(a[1]), "r"(a[2]), "r"(a[3]), "r"(b0), "r"(b1));
}
__device__ __forceinline__ void cpa16(uint32_t dst, const void* src) {
    asm volatile("cp.async.cg.shared.global [%0], [%1], 16;" :: "r"(dst), "l"(src));
}
#define CP_COMMIT() asm volatile("cp.async.commit_group;" ::: "memory")
#define CP_WAIT1()  asm volatile("cp.async.wait_group 1;" ::: "memory")

// A-operand ldmatrix addrs (16 rows x 16 k at (r0, chunk c0)), row-major,
// xor-swizzled 16B chunks: chunk' = chunk ^ (row & 7)
__device__ __forceinline__ uint32_t addrA(uint32_t base, int r0, int c0, int lane, int rowb) {
    int mi = lane >> 3;
    int row = r0 + (lane & 7) + ((mi & 1) << 3);
    int ch = c0 + (mi >> 1);
    return base + row * rowb + ((ch ^ (row & 7)) << 4);
}
// B-operand (16 n-rows x 16 k at (n0, chunk c0)), n-major
__device__ __forceinline__ uint32_t addrB(uint32_t base, int n0, int c0, int lane, int rowb) {
    int mi = lane >> 3;
    int row = n0 + (lane & 7) + ((mi >> 1) << 3);
    int ch = c0 + (mi & 1);
    return base + row * rowb + ((ch ^ (row & 7)) << 4);
}
__device__ __forceinline__ uint32_t pack_h2(float x, float y) {
    __half2 h = __floats2half2_rn(x, y);
    return *(uint32_t*)&h;
}

// ---------------------------------------------------------------------------
// Attn SMEM layout: resident Q fp16 (32KB); 3-stage buffers {K, V, c}
// ---------------------------------------------------------------------------
#define SQH  0
#define BUF0 32768
#define BUFSTRIDE 24832
#define OK   0        // 16384 (K fp16 swizzled, 256B rows)
#define OV   16384    // 8192  (V fp16 swizzled, 128B rows)
#define OGK  24576    // 256   (c_j f32)
#define SMEM_BYTES (32768 + 3 * 24832)   // 107264 -> 2 CTAs/SM

// ---------------------------------------------------------------------------
// Prep (z=0 query, z=1 keys): angles = x@W + b (fp32 FFMA, W cached in smem);
// phi = [cos,sin]/8 (keys *= sqrt(g)); g_gk = 1e-5*g.
// Prep (z=2): V transpose -> g_vt_h fp16.
// ---------------------------------------------------------------------------
__global__ __launch_bounds__(256) void prep_kernel(
    const float* __restrict__ q,
    const float* __restrict__ k,
    const float* __restrict__ v,
    const float* __restrict__ W,
    const float* __restrict__ b)
{
    __shared__ float xs[64 * 65];
    __shared__ float ws[64 * 64];
    __shared__ float sqg[64];

    const int bh = blockIdx.y;
    const int s0 = blockIdx.x * 64;
    const int z = blockIdx.z;
    const int tid = threadIdx.x;

    if (z == 2) {
        // --- V transpose branch ---
        for (int lin = tid; lin < 4096; lin += 256) {
            int s = lin >> 6, d = lin & 63;
            xs[s * 65 + d] = v[((size_t)bh * SQ + s0 + s) * DH + d];
        }
        __syncthreads();
        for (int lin = tid; lin < 4096; lin += 256) {
            int d = lin >> 6, s = lin & 63;
            g_vt_h[((size_t)bh * DH + d) * SQ + s0 + s] = __float2half_rn(xs[s * 65 + d]);
        }
        return;
    }

    const bool is_key = (z == 1);
    const float* src = (is_key ? k : q) + ((size_t)bh * SQ + s0) * DH;

    for (int lin = tid; lin < 64 * 64; lin += 256) {
        int row = lin >> 6, kk = lin & 63;
        xs[row * 65 + kk] = src[lin];
    }
    // W cached in smem once per CTA (16KB, linear copy)
    for (int i = tid; i < 1024; i += 256)
        *(float4*)(ws + i * 4) = *(const float4*)(W + i * 4);
    __syncthreads();

    const int tx = tid & 15, ty = tid >> 4;
    const int tx4 = tx * 4, ty4 = ty * 4;

    float bj[4];
#pragma unroll
    for (int j = 0; j < 4; j++) bj[j] = b[tx4 + j];
    float acc[4][4];
#pragma unroll
    for (int i = 0; i < 4; i++)
#pragma unroll
        for (int j = 0; j < 4; j++) acc[i][j] = bj[j];

#pragma unroll 4
    for (int kk = 0; kk < 64; kk++) {
        float a0 = xs[(ty4 + 0) * 65 + kk];
        float a1 = xs[(ty4 + 1) * 65 + kk];
        float a2 = xs[(ty4 + 2) * 65 + kk];
        float a3 = xs[(ty4 + 3) * 65 + kk];
        const float4 wv = *(const float4*)(ws + kk * 64 + tx4);
        acc[0][0] = fmaf(a0, wv.x, acc[0][0]); acc[0][1] = fmaf(a0, wv.y, acc[0][1]);
        acc[0][2] = fmaf(a0, wv.z, acc[0][2]); acc[0][3] = fmaf(a0, wv.w, acc[0][3]);
        acc[1][0] = fmaf(a1, wv.x, acc[1][0]); acc[1][1] = fmaf(a1, wv.y, acc[1][1]);
        acc[1][2] = fmaf(a1, wv.z, acc[1][2]); acc[1][3] = fmaf(a1, wv.w, acc[1][3]);
        acc[2][0] = fmaf(a2, wv.x, acc[2][0]); acc[2][1] = fmaf(a2, wv.y, acc[2][1]);
        acc[2][2] = fmaf(a2, wv.z, acc[2][2]); acc[2][3] = fmaf(a2, wv.w, acc[2][3]);
        acc[3][0] = fmaf(a3, wv.x, acc[3][0]); acc[3][1] = fmaf(a3, wv.y, acc[3][1]);
        acc[3][2] = fmaf(a3, wv.z, acc[3][2]); acc[3][3] = fmaf(a3, wv.w, acc[3][3]);
    }

    if (is_key && tid < 64) {
        float sum = 0.f;
#pragma unroll 8
        for (int kk = 0; kk < 64; kk++) {
            float vx = xs[tid * 65 + kk];
            sum = fmaf(vx, vx, sum);
        }
        sqg[tid] = __expf(sum * (1.0f / 32.0f));
        g_gk[bh * SQ + s0 + tid] = 1e-5f * __expf(sum * (1.0f / 16.0f));
    }
    __syncthreads();   // sqg ready

    __half* dst = (is_key ? g_phik_h : g_phiq_h);
#pragma unroll
    for (int i = 0; i < 4; i++) {
        const float scale = is_key ? (0.125f * sqg[ty4 + i]) : 0.125f;
        float c[4], s[4];
#pragma unroll
        for (int j = 0; j < 4; j++) {
            float sv, cv;
            __sincosf(acc[i][j], &sv, &cv);
            c[j] = cv * scale;
            s[j] = sv * scale;
        }
        size_t idx = ((size_t)bh * SQ + s0 + ty4 + i) * FF;
        uint2 cw = make_uint2(pack_h2(c[0], c[1]), pack_h2(c[2], c[3]));
        uint2 sw = make_uint2(pack_h2(s[0], s[1]), pack_h2(s[2], s[3]));
        *(uint2*)(dst + idx + tx4) = cw;
        *(uint2*)(dst + idx + 64 + tx4) = sw;
    }
}

// ---------------------------------------------------------------------------
// Attention: CTA = 128 query rows of one (b,h). R11 structure (Q via smem
// ldsm, 8 independent E chains) + explicit 1-deep B-fragment double-buffer
// in both GEMMs to overlap ldsm latency with mma issue.
// 3-stage cp.async pipeline, one __syncthreads per iteration, 2 CTAs/SM.
// ---------------------------------------------------------------------------
__global__ __launch_bounds__(256, 2) void attn_mma_kernel(
    float* __restrict__ out)
{
    extern __shared__ char smem[];
    const uint32_t base = smem_u32(smem);

    const int tid = threadIdx.x;
    const int wid = tid >> 5;
    const int lane = tid & 31;
    const int it = gridDim.x - 1 - blockIdx.x;   // longest CTAs first
    const int bh = blockIdx.y;
    const int i0 = it * TM;
    const int jt_max = 2 * it + 1;

    const __half* pkh = g_phik_h + (size_t)bh * SQ * FF;
    const __half* vth = g_vt_h + (size_t)bh * DH * SQ;
    const float* gk = g_gk + bh * SQ;

    // --- resident phiQ tile (fp16, swizzled 256B rows) ---
    {
        const __half* pqh = g_phiq_h + ((size_t)bh * SQ + i0) * FF;
        for (int i = tid; i < 128 * 16; i += 256) {
            int row = i >> 4, ch = i & 15;
            uint32_t off = row * 256 + ((ch ^ (row & 7)) << 4);
            *(uint4*)(smem + SQH + off) = *(const uint4*)(pqh + (size_t)row * FF + ch * 8);
        }
    }

    auto issue_tile = [&](int jt) {
        uint32_t buf = base + BUF0 + (uint32_t)(jt % 3) * BUFSTRIDE;
        int j0 = jt * TN;
        for (int i = tid; i < 1024; i += 256) {
            int row = i >> 4, ch = i & 15;
            uint32_t off = row * 256 + ((ch ^ (row & 7)) << 4);
            cpa16(buf + OK + off, pkh + (size_t)(j0 + row) * FF + ch * 8);
        }
        for (int i = tid; i < 512; i += 256) {
            int row = i >> 3, ch = i & 7;
            uint32_t off = row * 128 + ((ch ^ (row & 7)) << 4);
            cpa16(buf + OV + off, vth + (size_t)row * SQ + j0 + ch * 8);
        }
        if (tid < 16) cpa16(buf + OGK + tid * 16, gk + j0 + tid * 4);
    };

    issue_tile(0); CP_COMMIT();
    issue_tile(1); CP_COMMIT();

    float O[8][4];
#pragma unroll
    for (int n = 0; n < 8; n++)
#pragma unroll
        for (int j = 0; j < 4; j++) O[n][j] = 0.f;
    float rs0 = 0.f, rs1 = 0.f;

    const int mrow0 = i0 + wid * 16 + (lane >> 2);
    const int mrow1 = mrow0 + 8;
    const int colq = 2 * (lane & 3);

    for (int jt = 0; jt <= jt_max; jt++) {
        const int j0 = jt * TN;
        const uint32_t buf = base + BUF0 + (uint32_t)(jt % 3) * BUFSTRIDE;

        CP_WAIT1();
        __syncthreads();

        if (jt + 2 <= jt_max) issue_tile(jt + 2);
        CP_COMMIT();

        // ---- GEMM1: E = Q.K'^T with 1-deep B prefetch ----
        float E[8][4];
#pragma unroll
        for (int n = 0; n < 8; n++)
#pragma unroll
            for (int j = 0; j < 4; j++) E[n][j] = 0.f;

        uint32_t bq[2][4];
        ldsm4(bq[0], addrB(buf + OK, 0, 0, lane, 256));
#pragma unroll
        for (int ks = 0; ks < 8; ks++) {
            uint32_t a[4];
            ldsm4(a, addrA(base + SQH, wid * 16, 2 * ks, lane, 256));
#pragma unroll
            for (int np = 0; np < 4; np++) {
                const int cur = (ks * 4 + np) & 1;
                const int nidx = ks * 4 + np + 1;
                if (nidx < 32) {
                    ldsm4(bq[cur ^ 1],
                          addrB(buf + OK, (nidx & 3) * 16, 2 * (nidx >> 2), lane, 256));
                }
                mma_fp16(E[2 * np],     a, bq[cur][0], bq[cur][1]);
                mma_fp16(E[2 * np + 1], a, bq[cur][2], bq[cur][3]);
            }
        }

        // ---- epilogue: w = fma(E,E,c_j); mask only on diagonal tiles ----
        const float* ckb = (const float*)(smem + BUF0 + (size_t)(jt % 3) * BUFSTRIDE + OGK);
        if (j0 + TN - 1 <= i0) {
#pragma unroll
            for (int nt = 0; nt < 8; nt++) {
                float c0 = ckb[8 * nt + colq];
                float c1 = ckb[8 * nt + colq + 1];
                float w00 = fmaf(E[nt][0], E[nt][0], c0);
                float w01 = fmaf(E[nt][1], E[nt][1], c1);
                float w10 = fmaf(E[nt][2], E[nt][2], c0);
                float w11 = fmaf(E[nt][3], E[nt][3], c1);
                E[nt][0] = w00; E[nt][1] = w01; E[nt][2] = w10; E[nt][3] = w11;
                rs0 += w00 + w01;
                rs1 += w10 + w11;
            }
        } else {
#pragma unroll
            for (int nt = 0; nt < 8; nt++) {
                int jc = j0 + 8 * nt + colq;
                float c0 = ckb[8 * nt + colq];
                float c1 = ckb[8 * nt + colq + 1];
                float w00 = fmaf(E[nt][0], E[nt][0], c0);
                float w01 = fmaf(E[nt][1], E[nt][1], c1);
                float w10 = fmaf(E[nt][2], E[nt][2], c0);
                float w11 = fmaf(E[nt][3], E[nt][3], c1);
                if (jc > mrow0)     w00 = 0.f;
                if (jc + 1 > mrow0) w01 = 0.f;
                if (jc > mrow1)     w10 = 0.f;
                if (jc + 1 > mrow1) w11 = 0.f;
                E[nt][0] = w00; E[nt][1] = w01; E[nt][2] = w10; E[nt][3] = w11;
                rs0 += w00 + w01;
                rs1 += w10 + w11;
            }
        }

        // ---- GEMM2: O += W.V with 1-deep B prefetch ----
        uint32_t vq[2][4];
        ldsm4(vq[0], addrB(buf + OV, 0, 0, lane, 128));
#pragma unroll
        for (int s = 0; s < 4; s++) {
            uint32_t ah[4];
            ah[0] = pack_h2(E[2 * s][0],     E[2 * s][1]);
            ah[1] = pack_h2(E[2 * s][2],     E[2 * s][3]);
            ah[2] = pack_h2(E[2 * s + 1][0], E[2 * s + 1][1]);
            ah[3] = pack_h2(E[2 * s + 1][2], E[2 * s + 1][3]);
#pragma unroll
            for (int np = 0; np < 4; np++) {
                const int cur = (s * 4 + np) & 1;
                const int nidx = s * 4 + np + 1;
                if (nidx < 16) {
                    ldsm4(vq[cur ^ 1],
                          addrB(buf + OV, (nidx & 3) * 16, 2 * (nidx >> 2), lane, 128));
                }
                mma_fp16(O[2 * np],     ah, vq[cur][0], vq[cur][1]);
                mma_fp16(O[2 * np + 1], ah, vq[cur][2], vq[cur][3]);
            }
        }
    }

    // ---- final: reduce row sums across quad lanes, normalize, store ----
    rs0 += __shfl_xor_sync(0xffffffffu, rs0, 1);
    rs0 += __shfl_xor_sync(0xffffffffu, rs0, 2);
    rs1 += __shfl_xor_sync(0xffffffffu, rs1, 1);
    rs1 += __shfl_xor_sync(0xffffffffu, rs1, 2);
    const float inv0 = 1.0f / rs0;
    const float inv1 = 1.0f / rs1;

    float* o0 = out + ((size_t)bh * SQ + mrow0) * DH;
    float* o1 = out + ((size_t)bh * SQ + mrow1) * DH;
#pragma unroll
    for (int nt = 0; nt < 8; nt++) {
        int d = 8 * nt + colq;
        float2 v0 = make_float2(O[nt][0] * inv0, O[nt][1] * inv0);
        float2 v1 = make_float2(O[nt][2] * inv1, O[nt][3] * inv1);
        *(float2*)(o0 + d) = v0;
        *(float2*)(o1 + d) = v1;
    }
}

// ---------------------------------------------------------------------------
extern "C" void kernel_launch(void* const* d_in, const int* in_sizes, int n_in,
                              void* d_out, int out_size)
{
    const float* q = (const float*)d_in[0];
    const float* k = (const float*)d_in[1];
    const float* v = (const float*)d_in[2];
    // d_in[3] = mask (int32) — causal mask reproduced analytically, unused
    const float* W = (const float*)d_in[4];
    const float* b = (const float*)d_in[5];
    float* out = (float*)d_out;
    (void)in_sizes; (void)n_in; (void)out_size;

    cudaFuncSetAttribute(attn_mma_kernel, cudaFuncAttributeMaxDynamicSharedMemorySize, SMEM_BYTES);

    prep_kernel<<<dim3(SQ / 64, BHN, 3), 256>>>(q, k, v, W, b);
    attn_mma_kernel<<<dim3(SQ / TM, BHN), 256, SMEM_BYTES>>>(out);
}

// round 15
// speedup vs baseline: 1.1542x; 1.0101x over previous
#include <cuda_runtime.h>
#include <cuda_bf16.h>
#include <cuda_fp16.h>
#include <math.h>
#include <stdint.h>

// Problem constants: B=2, H=16 -> BH=32, S=2048, D=64, R=64 -> F=2R=128
#define SQ   2048
#define DH   64
#define FF   128
#define BHN  32
#define TM   128   // query rows per CTA
#define TN   64    // key cols per tile

// ---------------------------------------------------------------------------
// Global scratch. phi pre-scaled by 1/8; phik additionally scaled by sqrt(g_j)
// so E' = E*sqrt(g) and w = fma(E',E',c_j) with c_j = 1e-5*g_j.
// Q/K: single fp16, layout [bh][s][f]. V transposed fp16: [bh][d][s].
// ---------------------------------------------------------------------------
__device__ __half g_phiq_h[(size_t)BHN * SQ * FF];
__device__ __half g_phik_h[(size_t)BHN * SQ * FF];
__device__ __half g_vt_h[(size_t)BHN * DH * SQ];
__device__ float g_gk[BHN * SQ];   // c_j = 1e-5 * exp(||k||^2/16)

// ---------------------------------------------------------------------------
// Helpers (baseline ISA: mma.sync / ldmatrix / cp.async — compiles plain sm_100)
// ---------------------------------------------------------------------------
__device__ __forceinline__ uint32_t smem_u32(const void* p) {
    uint32_t a;
    asm("{ .reg .u64 t; cvta.to.shared.u64 t, %1; cvt.u32.u64 %0, t; }" : "=r"(a) : "l"(p));
    return a;
}
__device__ __forceinline__ void ldsm4(uint32_t* r, uint32_t addr) {
    asm volatile("ldmatrix.sync.aligned.m8n8.x4.shared.b16 {%0,%1,%2,%3}, [%4];"
        : "=r"(r[0]), "=r"(r[1]), "=r"(r[2]), "=r"(r[3]) : "r"(addr));
}
__device__ __forceinline__ void mma_fp16(float* c, const uint32_t* a, uint32_t b0, uint32_t b1) {
    asm volatile("mma.sync.aligned.m16n8k16.row.col.f32.f16.f16.f32 "
        "{%0,%1,%2,%3}, {%4,%5,%6,%7}, {%8,%9}, {%0,%1,%2,%3};"
        : "+f"(c[0]), "+f"(c[1]), "+f"(c[2]), "+f"(c[3])
        : "r"(a[0]), "r"(a[1]), "r"(a[2]), "r"(a[3]), "r"(b0), "r"(b1));
}
__device__ __forceinline__ void cpa16(uint32_t dst, const void* src) {
    asm volatile("cp.async.cg.shared.global [%0], [%1], 16;" :: "r"(dst), "l"(src));
}
#define CP_COMMIT() asm volatile("cp.async.commit_group;" ::: "memory")
#define CP_WAIT1()  asm volatile("cp.async.wait_group 1;" ::: "memory")

// A-operand ldmatrix addrs (16 rows x 16 k at (r0, chunk c0)), row-major,
// xor-swizzled 16B chunks: chunk' = chunk ^ (row & 7)
__device__ __forceinline__ uint32_t addrA(uint32_t base, int r0, int c0, int lane, int rowb) {
    int mi = lane >> 3;
    int row = r0 + (lane & 7) + ((mi & 1) << 3);
    int ch = c0 + (mi >> 1);
    return base + row * rowb + ((ch ^ (row & 7)) << 4);
}
// B-operand (16 n-rows x 16 k at (n0, chunk c0)), n-major
__device__ __forceinline__ uint32_t addrB(uint32_t base, int n0, int c0, int lane, int rowb) {
    int mi = lane >> 3;
    int row = n0 + (lane & 7) + ((mi >> 1) << 3);
    int ch = c0 + (mi & 1);
    return base + row * rowb + ((ch ^ (row & 7)) << 4);
}
__device__ __forceinline__ uint32_t pack_h2(float x, float y) {
    __half2 h = __floats2half2_rn(x, y);
    return *(uint32_t*)&h;
}

// ---------------------------------------------------------------------------
// Attn SMEM layout: resident Q fp16 (32KB); 3-stage buffers {K, V, c}
// ---------------------------------------------------------------------------
#define SQH  0
#define BUF0 32768
#define BUFSTRIDE 24832
#define OK   0        // 16384 (K fp16 swizzled, 256B rows)
#define OV   16384    // 8192  (V fp16 swizzled, 128B rows)
#define OGK  24576    // 256   (c_j f32)
#define SMEM_BYTES (32768 + 3 * 24832)   // 107264 -> 2 CTAs/SM

// ---------------------------------------------------------------------------
// Prep (z=0): BOTH query and key projection passes in one CTA (W smem load
// amortized). angles = x@W + b (fp32 FFMA); phi = [cos,sin]/8 (keys *=
// sqrt(g)); g_gk = 1e-5*g. Prep (z=1): V transpose -> g_vt_h fp16.
// ---------------------------------------------------------------------------
__global__ __launch_bounds__(256) void prep_kernel(
    const float* __restrict__ q,
    const float* __restrict__ k,
    const float* __restrict__ v,
    const float* __restrict__ W,
    const float* __restrict__ b)
{
    __shared__ float xs[64 * 65];
    __shared__ float ws[64 * 64];
    __shared__ float sqg[64];

    const int bh = blockIdx.y;
    const int s0 = blockIdx.x * 64;
    const int tid = threadIdx.x;

    if (blockIdx.z == 1) {
        // --- V transpose branch ---
        for (int lin = tid; lin < 4096; lin += 256) {
            int s = lin >> 6, d = lin & 63;
            xs[s * 65 + d] = v[((size_t)bh * SQ + s0 + s) * DH + d];
        }
        __syncthreads();
        for (int lin = tid; lin < 4096; lin += 256) {
            int d = lin >> 6, s = lin & 63;
            g_vt_h[((size_t)bh * DH + d) * SQ + s0 + s] = __float2half_rn(xs[s * 65 + d]);
        }
        return;
    }

    // W cached in smem once per CTA (16KB, linear copy)
    for (int i = tid; i < 1024; i += 256)
        *(float4*)(ws + i * 4) = *(const float4*)(W + i * 4);

    const int tx = tid & 15, ty = tid >> 4;
    const int tx4 = tx * 4, ty4 = ty * 4;

    float bj[4];
#pragma unroll
    for (int j = 0; j < 4; j++) bj[j] = b[tx4 + j];

#pragma unroll
    for (int pass = 0; pass < 2; pass++) {
        const bool is_key = (pass == 1);
        const float* src = (is_key ? k : q) + ((size_t)bh * SQ + s0) * DH;

        __syncthreads();   // previous pass done with xs/sqg
        for (int lin = tid; lin < 64 * 64; lin += 256) {
            int row = lin >> 6, kk = lin & 63;
            xs[row * 65 + kk] = src[lin];
        }
        __syncthreads();

        float acc[4][4];
#pragma unroll
        for (int i = 0; i < 4; i++)
#pragma unroll
            for (int j = 0; j < 4; j++) acc[i][j] = bj[j];

#pragma unroll 4
        for (int kk = 0; kk < 64; kk++) {
            float a0 = xs[(ty4 + 0) * 65 + kk];
            float a1 = xs[(ty4 + 1) * 65 + kk];
            float a2 = xs[(ty4 + 2) * 65 + kk];
            float a3 = xs[(ty4 + 3) * 65 + kk];
            const float4 wv = *(const float4*)(ws + kk * 64 + tx4);
            acc[0][0] = fmaf(a0, wv.x, acc[0][0]); acc[0][1] = fmaf(a0, wv.y, acc[0][1]);
            acc[0][2] = fmaf(a0, wv.z, acc[0][2]); acc[0][3] = fmaf(a0, wv.w, acc[0][3]);
            acc[1][0] = fmaf(a1, wv.x, acc[1][0]); acc[1][1] = fmaf(a1, wv.y, acc[1][1]);
            acc[1][2] = fmaf(a1, wv.z, acc[1][2]); acc[1][3] = fmaf(a1, wv.w, acc[1][3]);
            acc[2][0] = fmaf(a2, wv.x, acc[2][0]); acc[2][1] = fmaf(a2, wv.y, acc[2][1]);
            acc[2][2] = fmaf(a2, wv.z, acc[2][2]); acc[2][3] = fmaf(a2, wv.w, acc[2][3]);
            acc[3][0] = fmaf(a3, wv.x, acc[3][0]); acc[3][1] = fmaf(a3, wv.y, acc[3][1]);
            acc[3][2] = fmaf(a3, wv.z, acc[3][2]); acc[3][3] = fmaf(a3, wv.w, acc[3][3]);
        }

        if (is_key && tid < 64) {
            float sum = 0.f;
#pragma unroll 8
            for (int kk = 0; kk < 64; kk++) {
                float vx = xs[tid * 65 + kk];
                sum = fmaf(vx, vx, sum);
            }
            sqg[tid] = __expf(sum * (1.0f / 32.0f));
            g_gk[bh * SQ + s0 + tid] = 1e-5f * __expf(sum * (1.0f / 16.0f));
        }
        __syncthreads();   // sqg ready; xs reads done

        __half* dst = (is_key ? g_phik_h : g_phiq_h);
#pragma unroll
        for (int i = 0; i < 4; i++) {
            const float scale = is_key ? (0.125f * sqg[ty4 + i]) : 0.125f;
            float c[4], s[4];
#pragma unroll
            for (int j = 0; j < 4; j++) {
                float sv, cv;
                __sincosf(acc[i][j], &sv, &cv);
                c[j] = cv * scale;
                s[j] = sv * scale;
            }
            size_t idx = ((size_t)bh * SQ + s0 + ty4 + i) * FF;
            uint2 cw = make_uint2(pack_h2(c[0], c[1]), pack_h2(c[2], c[3]));
            uint2 sw = make_uint2(pack_h2(s[0], s[1]), pack_h2(s[2], s[3]));
            *(uint2*)(dst + idx + tx4) = cw;
            *(uint2*)(dst + idx + 64 + tx4) = sw;
        }
    }
}

// ---------------------------------------------------------------------------
// Attention: CTA = 128 query rows of one (b,h). SMEM-BW-bound design point:
// GEMM1 with 1-deep B prefetch; epilogue and GEMM2 interleaved per 16-col
// slice so GEMM2 mma resumes after 1/4 of the epilogue.
// 3-stage cp.async pipeline, one __syncthreads per iteration, 2 CTAs/SM.
// ---------------------------------------------------------------------------
__global__ __launch_bounds__(256, 2) void attn_mma_kernel(
    float* __restrict__ out)
{
    extern __shared__ char smem[];
    const uint32_t base = smem_u32(smem);

    const int tid = threadIdx.x;
    const int wid = tid >> 5;
    const int lane = tid & 31;
    const int it = gridDim.x - 1 - blockIdx.x;   // longest CTAs first
    const int bh = blockIdx.y;
    const int i0 = it * TM;
    const int jt_max = 2 * it + 1;

    const __half* pkh = g_phik_h + (size_t)bh * SQ * FF;
    const __half* vth = g_vt_h + (size_t)bh * DH * SQ;
    const float* gk = g_gk + bh * SQ;

    // --- resident phiQ tile (fp16, swizzled 256B rows) ---
    {
        const __half* pqh = g_phiq_h + ((size_t)bh * SQ + i0) * FF;
        for (int i = tid; i < 128 * 16; i += 256) {
            int row = i >> 4, ch = i & 15;
            uint32_t off = row * 256 + ((ch ^ (row & 7)) << 4);
            *(uint4*)(smem + SQH + off) = *(const uint4*)(pqh + (size_t)row * FF + ch * 8);
        }
    }

    auto issue_tile = [&](int jt) {
        uint32_t buf = base + BUF0 + (uint32_t)(jt % 3) * BUFSTRIDE;
        int j0 = jt * TN;
        for (int i = tid; i < 1024; i += 256) {
            int row = i >> 4, ch = i & 15;
            uint32_t off = row * 256 + ((ch ^ (row & 7)) << 4);
            cpa16(buf + OK + off, pkh + (size_t)(j0 + row) * FF + ch * 8);
        }
        for (int i = tid; i < 512; i += 256) {
            int row = i >> 3, ch = i & 7;
            uint32_t off = row * 128 + ((ch ^ (row & 7)) << 4);
            cpa16(buf + OV + off, vth + (size_t)row * SQ + j0 + ch * 8);
        }
        if (tid < 16) cpa16(buf + OGK + tid * 16, gk + j0 + tid * 4);
    };

    issue_tile(0); CP_COMMIT();
    issue_tile(1); CP_COMMIT();

    float O[8][4];
#pragma unroll
    for (int n = 0; n < 8; n++)
#pragma unroll
        for (int j = 0; j < 4; j++) O[n][j] = 0.f;
    float rs0 = 0.f, rs1 = 0.f;

    const int mrow0 = i0 + wid * 16 + (lane >> 2);
    const int mrow1 = mrow0 + 8;
    const int colq = 2 * (lane & 3);

    for (int jt = 0; jt <= jt_max; jt++) {
        const int j0 = jt * TN;
        const uint32_t buf = base + BUF0 + (uint32_t)(jt % 3) * BUFSTRIDE;

        CP_WAIT1();
        __syncthreads();

        if (jt + 2 <= jt_max) issue_tile(jt + 2);
        CP_COMMIT();

        // ---- GEMM1: E = Q.K'^T with 1-deep B prefetch ----
        float E[8][4];
#pragma unroll
        for (int n = 0; n < 8; n++)
#pragma unroll
            for (int j = 0; j < 4; j++) E[n][j] = 0.f;

        uint32_t bq[2][4];
        ldsm4(bq[0], addrB(buf + OK, 0, 0, lane, 256));
#pragma unroll
        for (int ks = 0; ks < 8; ks++) {
            uint32_t a[4];
            ldsm4(a, addrA(base + SQH, wid * 16, 2 * ks, lane, 256));
#pragma unroll
            for (int np = 0; np < 4; np++) {
                const int cur = (ks * 4 + np) & 1;
                const int nidx = ks * 4 + np + 1;
                if (nidx < 32) {
                    ldsm4(bq[cur ^ 1],
                          addrB(buf + OK, (nidx & 3) * 16, 2 * (nidx >> 2), lane, 256));
                }
                mma_fp16(E[2 * np],     a, bq[cur][0], bq[cur][1]);
                mma_fp16(E[2 * np + 1], a, bq[cur][2], bq[cur][3]);
            }
        }

        // ---- epilogue + GEMM2 interleaved per 16-col slice ----
        const float* ckb = (const float*)(smem + BUF0 + (size_t)(jt % 3) * BUFSTRIDE + OGK);
        uint32_t vq[2][4];
        ldsm4(vq[0], addrB(buf + OV, 0, 0, lane, 128));

        if (j0 + TN - 1 <= i0) {
            // fully unmasked tile
#pragma unroll
            for (int s = 0; s < 4; s++) {
#pragma unroll
                for (int t = 0; t < 2; t++) {
                    const int nt = 2 * s + t;
                    float c0 = ckb[8 * nt + colq];
                    float c1 = ckb[8 * nt + colq + 1];
                    float w00 = fmaf(E[nt][0], E[nt][0], c0);
                    float w01 = fmaf(E[nt][1], E[nt][1], c1);
                    float w10 = fmaf(E[nt][2], E[nt][2], c0);
                    float w11 = fmaf(E[nt][3], E[nt][3], c1);
                    E[nt][0] = w00; E[nt][1] = w01; E[nt][2] = w10; E[nt][3] = w11;
                    rs0 += w00 + w01;
                    rs1 += w10 + w11;
                }
                uint32_t ah[4];
                ah[0] = pack_h2(E[2 * s][0],     E[2 * s][1]);
                ah[1] = pack_h2(E[2 * s][2],     E[2 * s][3]);
                ah[2] = pack_h2(E[2 * s + 1][0], E[2 * s + 1][1]);
                ah[3] = pack_h2(E[2 * s + 1][2], E[2 * s + 1][3]);
#pragma unroll
                for (int np = 0; np < 4; np++) {
                    const int cur = (s * 4 + np) & 1;
                    const int nidx = s * 4 + np + 1;
                    if (nidx < 16) {
                        ldsm4(vq[cur ^ 1],
                              addrB(buf + OV, (nidx & 3) * 16, 2 * (nidx >> 2), lane, 128));
                    }
                    mma_fp16(O[2 * np],     ah, vq[cur][0], vq[cur][1]);
                    mma_fp16(O[2 * np + 1], ah, vq[cur][2], vq[cur][3]);
                }
            }
        } else {
#pragma unroll
            for (int s = 0; s < 4; s++) {
#pragma unroll
                for (int t = 0; t < 2; t++) {
                    const int nt = 2 * s + t;
                    int jc = j0 + 8 * nt + colq;
                    float c0 = ckb[8 * nt + colq];
                    float c1 = ckb[8 * nt + colq + 1];
                    float w00 = fmaf(E[nt][0], E[nt][0], c0);
                    float w01 = fmaf(E[nt][1], E[nt][1], c1);
                    float w10 = fmaf(E[nt][2], E[nt][2], c0);
                    float w11 = fmaf(E[nt][3], E[nt][3], c1);
                    if (jc > mrow0)     w00 = 0.f;
                    if (jc + 1 > mrow0) w01 = 0.f;
                    if (jc > mrow1)     w10 = 0.f;
                    if (jc + 1 > mrow1) w11 = 0.f;
                    E[nt][0] = w00; E[nt][1] = w01; E[nt][2] = w10; E[nt][3] = w11;
                    rs0 += w00 + w01;
                    rs1 += w10 + w11;
                }
                uint32_t ah[4];
                ah[0] = pack_h2(E[2 * s][0],     E[2 * s][1]);
                ah[1] = pack_h2(E[2 * s][2],     E[2 * s][3]);
                ah[2] = pack_h2(E[2 * s + 1][0], E[2 * s + 1][1]);
                ah[3] = pack_h2(E[2 * s + 1][2], E[2 * s + 1][3]);
#pragma unroll
                for (int np = 0; np < 4; np++) {
                    const int cur = (s * 4 + np) & 1;
                    const int nidx = s * 4 + np + 1;
                    if (nidx < 16) {
                        ldsm4(vq[cur ^ 1],
                              addrB(buf + OV, (nidx & 3) * 16, 2 * (nidx >> 2), lane, 128));
                    }
                    mma_fp16(O[2 * np],     ah, vq[cur][0], vq[cur][1]);
                    mma_fp16(O[2 * np + 1], ah, vq[cur][2], vq[cur][3]);
                }
            }
        }
    }

    // ---- final: reduce row sums across quad lanes, normalize, store ----
    rs0 += __shfl_xor_sync(0xffffffffu, rs0, 1);
    rs0 += __shfl_xor_sync(0xffffffffu, rs0, 2);
    rs1 += __shfl_xor_sync(0xffffffffu, rs1, 1);
    rs1 += __shfl_xor_sync(0xffffffffu, rs1, 2);
    const float inv0 = 1.0f / rs0;
    const float inv1 = 1.0f / rs1;

    float* o0 = out + ((size_t)bh * SQ + mrow0) * DH;
    float* o1 = out + ((size_t)bh * SQ + mrow1) * DH;
#pragma unroll
    for (int nt = 0; nt < 8; nt++) {
        int d = 8 * nt + colq;
        float2 v0 = make_float2(O[nt][0] * inv0, O[nt][1] * inv0);
        float2 v1 = make_float2(O[nt][2] * inv1, O[nt][3] * inv1);
        *(float2*)(o0 + d) = v0;
        *(float2*)(o1 + d) = v1;
    }
}

// ---------------------------------------------------------------------------
extern "C" void kernel_launch(void* const* d_in, const int* in_sizes, int n_in,
                              void* d_out, int out_size)
{
    const float* q = (const float*)d_in[0];
    const float* k = (const float*)d_in[1];
    const float* v = (const float*)d_in[2];
    // d_in[3] = mask (int32) — causal mask reproduced analytically, unused
    const float* W = (const float*)d_in[4];
    const float* b = (const float*)d_in[5];
    float* out = (float*)d_out;
    (void)in_sizes; (void)n_in; (void)out_size;

    cudaFuncSetAttribute(attn_mma_kernel, cudaFuncAttributeMaxDynamicSharedMemorySize, SMEM_BYTES);

    prep_kernel<<<dim3(SQ / 64, BHN, 2), 256>>>(q, k, v, W, b);
    attn_mma_kernel<<<dim3(SQ / TM, BHN), 256, SMEM_BYTES>>>(out);
}

// round 16
// speedup vs baseline: 1.2217x; 1.0584x over previous
#include <cuda_runtime.h>
#include <cuda_bf16.h>
#include <cuda_fp16.h>
#include <math.h>
#include <stdint.h>

// Problem constants: B=2, H=16 -> BH=32, S=2048, D=64, R=64 -> F=2R=128
#define SQ   2048
#define DH   64
#define FF   128
#define BHN  32
#define TM   128   // query rows per CTA
#define TN   64    // key cols per tile

// ---------------------------------------------------------------------------
// Global scratch. phi pre-scaled by 1/8; phik additionally scaled by sqrt(g_j)
// so E' = E*sqrt(g) and w = fma(E',E',c_j) with c_j = 1e-5*g_j.
// Q/K: single fp16, layout [bh][s][f]. V transposed fp16: [bh][d][s].
// g_wt: W^T fp16, ldsm-B-ready swizzled 128B rows (validated layout from R11).
// ---------------------------------------------------------------------------
__device__ __half g_phiq_h[(size_t)BHN * SQ * FF];
__device__ __half g_phik_h[(size_t)BHN * SQ * FF];
__device__ __half g_vt_h[(size_t)BHN * DH * SQ];
__device__ float g_gk[BHN * SQ];   // c_j = 1e-5 * exp(||k||^2/16)
__device__ __half g_wt[DH * DH];

// ---------------------------------------------------------------------------
// Helpers (baseline ISA: mma.sync / ldmatrix / cp.async — compiles plain sm_100)
// ---------------------------------------------------------------------------
__device__ __forceinline__ uint32_t smem_u32(const void* p) {
    uint32_t a;
    asm("{ .reg .u64 t; cvta.to.shared.u64 t, %1; cvt.u32.u64 %0, t; }" : "=r"(a) : "l"(p));
    return a;
}
__device__ __forceinline__ void ldsm4(uint32_t* r, uint32_t addr) {
    asm volatile("ldmatrix.sync.aligned.m8n8.x4.shared.b16 {%0,%1,%2,%3}, [%4];"
        : "=r"(r[0]), "=r"(r[1]), "=r"(r[2]), "=r"(r[3]) : "r"(addr));
}
__device__ __forceinline__ void mma_fp16(float* c, const uint32_t* a, uint32_t b0, uint32_t b1) {
    asm volatile("mma.sync.aligned.m16n8k16.row.col.f32.f16.f16.f32 "
        "{%0,%1,%2,%3}, {%4,%5,%6,%7}, {%8,%9}, {%0,%1,%2,%3};"
        : "+f"(c[0]), "+f"(c[1]), "+f"(c[2]), "+f"(c[3])
        : "r"(a[0]), "r"(a[1]), "r"(a[2]), "r"(a[3]), "r"(b0), "r"(b1));
}
__device__ __forceinline__ void cpa16(uint32_t dst, const void* src) {
    asm volatile("cp.async.cg.shared.global [%0], [%1], 16;" :: "r"(dst), "l"(src));
}
#define CP_COMMIT() asm volatile("cp.async.commit_group;" ::: "memory")
#define CP_WAIT1()  asm volatile("cp.async.wait_group 1;" ::: "memory")

// A-operand ldmatrix addrs (16 rows x 16 k at (r0, chunk c0)), row-major,
// xor-swizzled 16B chunks: chunk' = chunk ^ (row & 7)
__device__ __forceinline__ uint32_t addrA(uint32_t base, int r0, int c0, int lane, int rowb) {
    int mi = lane >> 3;
    int row = r0 + (lane & 7) + ((mi & 1) << 3);
    int ch = c0 + (mi >> 1);
    return base + row * rowb + ((ch ^ (row & 7)) << 4);
}
// B-operand (16 n-rows x 16 k at (n0, chunk c0)), n-major
__device__ __forceinline__ uint32_t addrB(uint32_t base, int n0, int c0, int lane, int rowb) {
    int mi = lane >> 3;
    int row = n0 + (lane & 7) + ((mi >> 1) << 3);
    int ch = c0 + (mi & 1);
    return base + row * rowb + ((ch ^ (row & 7)) << 4);
}
__device__ __forceinline__ uint32_t pack_h2(float x, float y) {
    __half2 h = __floats2half2_rn(x, y);
    return *(uint32_t*)&h;
}

// ---------------------------------------------------------------------------
// Attn SMEM layout: resident Q fp16 (32KB); 3-stage buffers {K, V, c}
// ---------------------------------------------------------------------------
#define SQH  0
#define BUF0 32768
#define BUFSTRIDE 24832
#define OK   0        // 16384 (K fp16 swizzled, 256B rows)
#define OV   16384    // 8192  (V fp16 swizzled, 128B rows)
#define OGK  24576    // 256   (c_j f32)
#define SMEM_BYTES (32768 + 3 * 24832)   // 107264 -> 2 CTAs/SM

// ---------------------------------------------------------------------------
// W^T prep: W[k][n] f32 -> g_wt[n][k] fp16, ldsm-B swizzled 128B rows.
// (Layout hardware-validated in R11's prep.) Single block.
// ---------------------------------------------------------------------------
__global__ __launch_bounds__(256) void wt_prep_kernel(const float* __restrict__ W)
{
    __shared__ float t[64][65];
    const int tid = threadIdx.x;
    for (int i = tid; i < 4096; i += 256) {
        int kk = i >> 6, n = i & 63;
        t[kk][n] = W[i];
    }
    __syncthreads();
    for (int i = tid; i < 4096; i += 256) {
        int n = i >> 6, kk = i & 63;
        uint32_t off = n * 128 + (((kk >> 3) ^ (n & 7)) << 4) + (kk & 7) * 2;
        *(__half*)((char*)g_wt + off) = __float2half_rn(t[kk][n]);
    }
}

// ---------------------------------------------------------------------------
// Prep (z=0): fused q+k projection via single-pass fp16 mma.
//   A = [q rows 0-63 | k rows 64-127] fp16 (converted during load), swizzled.
//   B = W^T from g_wt. angles = A.W + b; phi = [cos,sin]/8 (k *= sqrt(g)).
//   k-tile mirrored to f32 smem for exact norms; g_gk = 1e-5*g.
// Prep (z=1): V transpose -> g_vt_h fp16.
// ---------------------------------------------------------------------------
__global__ __launch_bounds__(256) void prep_kernel(
    const float* __restrict__ q,
    const float* __restrict__ k,
    const float* __restrict__ v,
    const float* __restrict__ b)
{
    __shared__ __half As[128 * 64];   // 16KB swizzled A (128B rows)
    __shared__ __half Bw[64 * 64];    // 8KB  swizzled B
    __shared__ float xk[64 * 68];     // k-tile f32 (stride 68 -> aligned f4)
    __shared__ float sb[64];
    __shared__ float sqg[64];

    const uint32_t baseA = smem_u32(As);
    const uint32_t baseB = smem_u32(Bw);

    const int bh = blockIdx.y;
    const int s0 = blockIdx.x * 64;
    const int tid = threadIdx.x;
    const int wid = tid >> 5;
    const int lane = tid & 31;

    if (blockIdx.z == 1) {
        // --- V transpose branch (uses xk as staging, stride 65, scalar) ---
        float* t = xk;
        for (int lin = tid; lin < 4096; lin += 256) {
            int s = lin >> 6, d = lin & 63;
            t[s * 65 + d] = v[((size_t)bh * SQ + s0 + s) * DH + d];
        }
        __syncthreads();
        for (int lin = tid; lin < 4096; lin += 256) {
            int d = lin >> 6, s = lin & 63;
            g_vt_h[((size_t)bh * DH + d) * SQ + s0 + s] = __float2half_rn(t[s * 65 + d]);
        }
        return;
    }

    // --- load q+k rows, convert to fp16 into swizzled A; mirror k f32 ---
    const float* qrow = q + ((size_t)bh * SQ + s0) * DH;
    const float* krow = k + ((size_t)bh * SQ + s0) * DH;
    for (int i = tid; i < 128 * 8; i += 256) {
        int row = i >> 3, ch = i & 7;
        const float* src = (row < 64) ? (qrow + (size_t)row * DH + ch * 8)
                                      : (krow + (size_t)(row - 64) * DH + ch * 8);
        float4 f0 = *(const float4*)src;
        float4 f1 = *(const float4*)(src + 4);
        uint4 u = make_uint4(pack_h2(f0.x, f0.y), pack_h2(f0.z, f0.w),
                             pack_h2(f1.x, f1.y), pack_h2(f1.z, f1.w));
        *(uint4*)((char*)As + row * 128 + ((ch ^ (row & 7)) << 4)) = u;
        if (row >= 64) {
            float* d = xk + (row - 64) * 68 + ch * 8;
            *(float4*)d = f0;
            *(float4*)(d + 4) = f1;
        }
    }
    // --- copy W^T fragments (pre-swizzled) linearly; bias ---
    for (int i = tid; i < 512; i += 256)
        *(uint4*)((char*)Bw + i * 16) = ((const uint4*)g_wt)[i];
    if (tid < 64) sb[tid] = b[tid];
    __syncthreads();

    // --- k norms (f32 exact) ---
    if (tid < 64) {
        float sum = 0.f;
#pragma unroll 8
        for (int kk = 0; kk < 64; kk++) {
            float vx = xk[tid * 68 + kk];
            sum = fmaf(vx, vx, sum);
        }
        sqg[tid] = __expf(sum * (1.0f / 32.0f));
        g_gk[bh * SQ + s0 + tid] = 1e-5f * __expf(sum * (1.0f / 16.0f));
    }
    __syncthreads();

    // --- GEMM: angles[128x64] = A.W^T, warp wid covers rows wid*16..+15 ---
    float E[8][4];
#pragma unroll
    for (int n = 0; n < 8; n++)
#pragma unroll
        for (int j = 0; j < 4; j++) E[n][j] = 0.f;

#pragma unroll
    for (int ks = 0; ks < 4; ks++) {
        uint32_t a[4];
        ldsm4(a, addrA(baseA, wid * 16, 2 * ks, lane, 128));
#pragma unroll
        for (int ng = 0; ng < 4; ng++) {
            uint32_t bq[4];
            ldsm4(bq, addrB(baseB, ng * 16, 2 * ks, lane, 128));
            mma_fp16(E[2 * ng],     a, bq[0], bq[1]);
            mma_fp16(E[2 * ng + 1], a, bq[2], bq[3]);
        }
    }

    // --- epilogue: bias + sincos + scale + pack + store ---
    const bool is_key = (wid >= 4);
    const int r0 = wid * 16 + (lane >> 2);           // 0..127
    const int lrow0 = r0 - (is_key ? 64 : 0);        // local row in q/k tile
    const int colq = 2 * (lane & 3);
    const float sc0 = is_key ? (0.125f * sqg[lrow0])     : 0.125f;
    const float sc1 = is_key ? (0.125f * sqg[lrow0 + 8]) : 0.125f;
    __half* dst = is_key ? g_phik_h : g_phiq_h;
    __half* d0 = dst + ((size_t)bh * SQ + s0 + lrow0) * FF;
    __half* d1 = dst + ((size_t)bh * SQ + s0 + lrow0 + 8) * FF;

#pragma unroll
    for (int nt = 0; nt < 8; nt++) {
        int col = nt * 8 + colq;
        float b0 = sb[col], b1 = sb[col + 1];
        float s00, c00, s01, c01, s10, c10, s11, c11;
        __sincosf(E[nt][0] + b0, &s00, &c00);
        __sincosf(E[nt][1] + b1, &s01, &c01);
        __sincosf(E[nt][2] + b0, &s10, &c10);
        __sincosf(E[nt][3] + b1, &s11, &c11);
        *(uint32_t*)(d0 + col)      = pack_h2(c00 * sc0, c01 * sc0);
        *(uint32_t*)(d0 + 64 + col) = pack_h2(s00 * sc0, s01 * sc0);
        *(uint32_t*)(d1 + col)      = pack_h2(c10 * sc1, c11 * sc1);
        *(uint32_t*)(d1 + 64 + col) = pack_h2(s10 * sc1, s11 * sc1);
    }
}

// ---------------------------------------------------------------------------
// Attention (unchanged from R15 best): CTA = 128 query rows of one (b,h).
// GEMM1 with 1-deep B prefetch; epilogue and GEMM2 interleaved per 16-col
// slice. 3-stage cp.async pipeline, one __syncthreads per iter, 2 CTAs/SM.
// ---------------------------------------------------------------------------
__global__ __launch_bounds__(256, 2) void attn_mma_kernel(
    float* __restrict__ out)
{
    extern __shared__ char smem[];
    const uint32_t base = smem_u32(smem);

    const int tid = threadIdx.x;
    const int wid = tid >> 5;
    const int lane = tid & 31;
    const int it = gridDim.x - 1 - blockIdx.x;   // longest CTAs first
    const int bh = blockIdx.y;
    const int i0 = it * TM;
    const int jt_max = 2 * it + 1;

    const __half* pkh = g_phik_h + (size_t)bh * SQ * FF;
    const __half* vth = g_vt_h + (size_t)bh * DH * SQ;
    const float* gk = g_gk + bh * SQ;

    // --- resident phiQ tile (fp16, swizzled 256B rows) ---
    {
        const __half* pqh = g_phiq_h + ((size_t)bh * SQ + i0) * FF;
        for (int i = tid; i < 128 * 16; i += 256) {
            int row = i >> 4, ch = i & 15;
            uint32_t off = row * 256 + ((ch ^ (row & 7)) << 4);
            *(uint4*)(smem + SQH + off) = *(const uint4*)(pqh + (size_t)row * FF + ch * 8);
        }
    }

    auto issue_tile = [&](int jt) {
        uint32_t buf = base + BUF0 + (uint32_t)(jt % 3) * BUFSTRIDE;
        int j0 = jt * TN;
        for (int i = tid; i < 1024; i += 256) {
            int row = i >> 4, ch = i & 15;
            uint32_t off = row * 256 + ((ch ^ (row & 7)) << 4);
            cpa16(buf + OK + off, pkh + (size_t)(j0 + row) * FF + ch * 8);
        }
        for (int i = tid; i < 512; i += 256) {
            int row = i >> 3, ch = i & 7;
            uint32_t off = row * 128 + ((ch ^ (row & 7)) << 4);
            cpa16(buf + OV + off, vth + (size_t)row * SQ + j0 + ch * 8);
        }
        if (tid < 16) cpa16(buf + OGK + tid * 16, gk + j0 + tid * 4);
    };

    issue_tile(0); CP_COMMIT();
    issue_tile(1); CP_COMMIT();

    float O[8][4];
#pragma unroll
    for (int n = 0; n < 8; n++)
#pragma unroll
        for (int j = 0; j < 4; j++) O[n][j] = 0.f;
    float rs0 = 0.f, rs1 = 0.f;

    const int mrow0 = i0 + wid * 16 + (lane >> 2);
    const int mrow1 = mrow0 + 8;
    const int colq = 2 * (lane & 3);

    for (int jt = 0; jt <= jt_max; jt++) {
        const int j0 = jt * TN;
        const uint32_t buf = base + BUF0 + (uint32_t)(jt % 3) * BUFSTRIDE;

        CP_WAIT1();
        __syncthreads();

        if (jt + 2 <= jt_max) issue_tile(jt + 2);
        CP_COMMIT();

        // ---- GEMM1: E = Q.K'^T with 1-deep B prefetch ----
        float E[8][4];
#pragma unroll
        for (int n = 0; n < 8; n++)
#pragma unroll
            for (int j = 0; j < 4; j++) E[n][j] = 0.f;

        uint32_t bq[2][4];
        ldsm4(bq[0], addrB(buf + OK, 0, 0, lane, 256));
#pragma unroll
        for (int ks = 0; ks < 8; ks++) {
            uint32_t a[4];
            ldsm4(a, addrA(base + SQH, wid * 16, 2 * ks, lane, 256));
#pragma unroll
            for (int np = 0; np < 4; np++) {
                const int cur = (ks * 4 + np) & 1;
                const int nidx = ks * 4 + np + 1;
                if (nidx < 32) {
                    ldsm4(bq[cur ^ 1],
                          addrB(buf + OK, (nidx & 3) * 16, 2 * (nidx >> 2), lane, 256));
                }
                mma_fp16(E[2 * np],     a, bq[cur][0], bq[cur][1]);
                mma_fp16(E[2 * np + 1], a, bq[cur][2], bq[cur][3]);
            }
        }

        // ---- epilogue + GEMM2 interleaved per 16-col slice ----
        const float* ckb = (const float*)(smem + BUF0 + (size_t)(jt % 3) * BUFSTRIDE + OGK);
        uint32_t vq[2][4];
        ldsm4(vq[0], addrB(buf + OV, 0, 0, lane, 128));

        if (j0 + TN - 1 <= i0) {
#pragma unroll
            for (int s = 0; s < 4; s++) {
#pragma unroll
                for (int t = 0; t < 2; t++) {
                    const int nt = 2 * s + t;
                    float c0 = ckb[8 * nt + colq];
                    float c1 = ckb[8 * nt + colq + 1];
                    float w00 = fmaf(E[nt][0], E[nt][0], c0);
                    float w01 = fmaf(E[nt][1], E[nt][1], c1);
                    float w10 = fmaf(E[nt][2], E[nt][2], c0);
                    float w11 = fmaf(E[nt][3], E[nt][3], c1);
                    E[nt][0] = w00; E[nt][1] = w01; E[nt][2] = w10; E[nt][3] = w11;
                    rs0 += w00 + w01;
                    rs1 += w10 + w11;
                }
                uint32_t ah[4];
                ah[0] = pack_h2(E[2 * s][0],     E[2 * s][1]);
                ah[1] = pack_h2(E[2 * s][2],     E[2 * s][3]);
                ah[2] = pack_h2(E[2 * s + 1][0], E[2 * s + 1][1]);
                ah[3] = pack_h2(E[2 * s + 1][2], E[2 * s + 1][3]);
#pragma unroll
                for (int np = 0; np < 4; np++) {
                    const int cur = (s * 4 + np) & 1;
                    const int nidx = s * 4 + np + 1;
                    if (nidx < 16) {
                        ldsm4(vq[cur ^ 1],
                              addrB(buf + OV, (nidx & 3) * 16, 2 * (nidx >> 2), lane, 128));
                    }
                    mma_fp16(O[2 * np],     ah, vq[cur][0], vq[cur][1]);
                    mma_fp16(O[2 * np + 1], ah, vq[cur][2], vq[cur][3]);
                }
            }
        } else {
#pragma unroll
            for (int s = 0; s < 4; s++) {
#pragma unroll
                for (int t = 0; t < 2; t++) {
                    const int nt = 2 * s + t;
                    int jc = j0 + 8 * nt + colq;
                    float c0 = ckb[8 * nt + colq];
                    float c1 = ckb[8 * nt + colq + 1];
                    float w00 = fmaf(E[nt][0], E[nt][0], c0);
                    float w01 = fmaf(E[nt][1], E[nt][1], c1);
                    float w10 = fmaf(E[nt][2], E[nt][2], c0);
                    float w11 = fmaf(E[nt][3], E[nt][3], c1);
                    if (jc > mrow0)     w00 = 0.f;
                    if (jc + 1 > mrow0) w01 = 0.f;
                    if (jc > mrow1)     w10 = 0.f;
                    if (jc + 1 > mrow1) w11 = 0.f;
                    E[nt][0] = w00; E[nt][1] = w01; E[nt][2] = w10; E[nt][3] = w11;
                    rs0 += w00 + w01;
                    rs1 += w10 + w11;
                }
                uint32_t ah[4];
                ah[0] = pack_h2(E[2 * s][0],     E[2 * s][1]);
                ah[1] = pack_h2(E[2 * s][2],     E[2 * s][3]);
                ah[2] = pack_h2(E[2 * s + 1][0], E[2 * s + 1][1]);
                ah[3] = pack_h2(E[2 * s + 1][2], E[2 * s + 1][3]);
#pragma unroll
                for (int np = 0; np < 4; np++) {
                    const int cur = (s * 4 + np) & 1;
                    const int nidx = s * 4 + np + 1;
                    if (nidx < 16) {
                        ldsm4(vq[cur ^ 1],
                              addrB(buf + OV, (nidx & 3) * 16, 2 * (nidx >> 2), lane, 128));
                    }
                    mma_fp16(O[2 * np],     ah, vq[cur][0], vq[cur][1]);
                    mma_fp16(O[2 * np + 1], ah, vq[cur][2], vq[cur][3]);
                }
            }
        }
    }

    // ---- final: reduce row sums across quad lanes, normalize, store ----
    rs0 += __shfl_xor_sync(0xffffffffu, rs0, 1);
    rs0 += __shfl_xor_sync(0xffffffffu, rs0, 2);
    rs1 += __shfl_xor_sync(0xffffffffu, rs1, 1);
    rs1 += __shfl_xor_sync(0xffffffffu, rs1, 2);
    const float inv0 = 1.0f / rs0;
    const float inv1 = 1.0f / rs1;

    float* o0 = out + ((size_t)bh * SQ + mrow0) * DH;
    float* o1 = out + ((size_t)bh * SQ + mrow1) * DH;
#pragma unroll
    for (int nt = 0; nt < 8; nt++) {
        int d = 8 * nt + colq;
        float2 v0 = make_float2(O[nt][0] * inv0, O[nt][1] * inv0);
        float2 v1 = make_float2(O[nt][2] * inv1, O[nt][3] * inv1);
        *(float2*)(o0 + d) = v0;
        *(float2*)(o1 + d) = v1;
    }
}

// ---------------------------------------------------------------------------
extern "C" void kernel_launch(void* const* d_in, const int* in_sizes, int n_in,
                              void* d_out, int out_size)
{
    const float* q = (const float*)d_in[0];
    const float* k = (const float*)d_in[1];
    const float* v = (const float*)d_in[2];
    // d_in[3] = mask (int32) — causal mask reproduced analytically, unused
    const float* W = (const float*)d_in[4];
    const float* b = (const float*)d_in[5];
    float* out = (float*)d_out;
    (void)in_sizes; (void)n_in; (void)out_size;

    cudaFuncSetAttribute(attn_mma_kernel, cudaFuncAttributeMaxDynamicSharedMemorySize, SMEM_BYTES);

    wt_prep_kernel<<<1, 256>>>(W);
    prep_kernel<<<dim3(SQ / 64, BHN, 2), 256>>>(q, k, v, b);
    attn_mma_kernel<<<dim3(SQ / TM, BHN), 256, SMEM_BYTES>>>(out);
}